// round 1
// baseline (speedup 1.0000x reference)
#include <cuda_runtime.h>
#include <cuda_bf16.h>
#include <math.h>
#include <stdint.h>

// ---------------------------------------------------------------------------
// MoE + LoRA forward, routed sparsely (top-2 of 8 experts).
//   out = hidden + alpha * sum_k gate_k * expert_{e_k}(x)
//   expert(x): g = x@gw.T + S*(x@gA.T)@gB.T ; u likewise ; a = silu(g)*u
//              d = a@dw.T + S*(a@dA.T)@dB.T
// LoRA folded into the GEMM as a K-extension block (K: 2048 -> 2080, last 16
// cols = prescaled projection P against loraB).
// ---------------------------------------------------------------------------

#define DIM    2048
#define T_TOK  8192
#define NE     8
#define NR     16
#define NROWS  (T_TOK*2)      // total token-expert pairs (exactly T*K)
#define SCALING 2.0f
#define AUXC   0.01f
#define ZC     0.001f

#define BM 128
#define BN 128
#define BK 32
#define NST (DIM/BK + 1)      // 65 stages; last stage = LoRA block
#define APAD (BK+8)           // smem row stride in halves (bank-friendly)

// ------------------------- scratch (device globals) ------------------------
__device__ int   g_counts[NE];
__device__ int   g_offsets[NE+1];
__device__ float g_importance[NE];
__device__ float g_zsum;
__device__ int   g_tok[NE*T_TOK];     // slot -> token id, per expert
__device__ int   g_re[NROWS];         // per token: expert ids (2)
__device__ int   g_rs[NROWS];         // per token: slots (2)
__device__ float g_rg[NROWS];         // per token: gate values (2)
__device__ float g_Pg[(size_t)NROWS*NR];
__device__ float g_Pu[(size_t)NROWS*NR];
__device__ float g_Pd[(size_t)NROWS*NR];
__device__ float g_G[(size_t)NROWS*DIM];            // gate branch pre-act
__device__ __nv_bfloat16 g_A2[(size_t)NROWS*DIM];   // silu(g)*u, bf16
__device__ float g_D[(size_t)NROWS*DIM];            // down output

// ------------------------------- helpers -----------------------------------
__device__ __forceinline__ uint2 cvt4(float4 v) {
    __nv_bfloat162 lo = __floats2bfloat162_rn(v.x, v.y);
    __nv_bfloat162 hi = __floats2bfloat162_rn(v.z, v.w);
    uint2 r;
    r.x = *reinterpret_cast<unsigned*>(&lo);
    r.y = *reinterpret_cast<unsigned*>(&hi);
    return r;
}

__device__ __forceinline__ void mma16816(float* d, const unsigned* a, const unsigned* b) {
    asm volatile(
        "mma.sync.aligned.m16n8k16.row.col.f32.bf16.bf16.f32 "
        "{%0,%1,%2,%3}, {%4,%5,%6,%7}, {%8,%9}, {%0,%1,%2,%3};\n"
        : "+f"(d[0]), "+f"(d[1]), "+f"(d[2]), "+f"(d[3])
        : "r"(a[0]), "r"(a[1]), "r"(a[2]), "r"(a[3]), "r"(b[0]), "r"(b[1]));
}

// ------------------------------- kernels ------------------------------------
__global__ void init_kernel() {
    int t = threadIdx.x;
    if (t < NE) { g_counts[t] = 0; g_importance[t] = 0.f; }
    if (t == 0) g_zsum = 0.f;
}

// One warp per token: 8 logits, top-2, softmax, loss stats, slot assignment.
__global__ void router_kernel(const float* __restrict__ X,
                              const float* __restrict__ Wg) {
    int warp = threadIdx.x >> 5, lane = threadIdx.x & 31;
    int t = blockIdx.x * 8 + warp;
    if (t >= T_TOK) return;
    const float4* xr = (const float4*)(X + (size_t)t * DIM);
    float acc[NE];
#pragma unroll
    for (int e = 0; e < NE; e++) acc[e] = 0.f;
    for (int i = lane; i < DIM/4; i += 32) {
        float4 xv = xr[i];
#pragma unroll
        for (int e = 0; e < NE; e++) {
            float4 w = ((const float4*)(Wg + (size_t)e * DIM))[i];
            acc[e] += xv.x*w.x + xv.y*w.y + xv.z*w.z + xv.w*w.w;
        }
    }
#pragma unroll
    for (int e = 0; e < NE; e++)
#pragma unroll
        for (int o = 16; o > 0; o >>= 1)
            acc[e] += __shfl_xor_sync(0xffffffffu, acc[e], o);

    if (lane == 0) {
        int e0 = 0;
#pragma unroll
        for (int e = 1; e < NE; e++) if (acc[e] > acc[e0]) e0 = e;
        int e1 = (e0 == 0) ? 1 : 0;
#pragma unroll
        for (int e = 0; e < NE; e++)
            if (e != e0 && acc[e] > acc[e1]) e1 = e;

        float m = acc[e0];
        float s = 0.f;
#pragma unroll
        for (int e = 0; e < NE; e++) s += expf(acc[e] - m);
        float lse = logf(s) + m;
        atomicAdd(&g_zsum, lse * lse);

        float d = expf(acc[e1] - acc[e0]);   // <= 1
        float p0 = 1.f / (1.f + d);
        float p1 = d / (1.f + d);

        int s0 = atomicAdd(&g_counts[e0], 1);
        int s1 = atomicAdd(&g_counts[e1], 1);
        g_tok[e0*T_TOK + s0] = t;
        g_tok[e1*T_TOK + s1] = t;
        atomicAdd(&g_importance[e0], p0);
        atomicAdd(&g_importance[e1], p1);
        g_re[2*t] = e0;  g_rs[2*t] = s0;  g_rg[2*t] = p0;
        g_re[2*t+1] = e1; g_rs[2*t+1] = s1; g_rg[2*t+1] = p1;
    }
}

__global__ void offsets_kernel() {
    if (threadIdx.x == 0) {
        int o = 0;
        for (int e = 0; e < NE; e++) { g_offsets[e] = o; o += g_counts[e]; }
        g_offsets[NE] = o;
    }
}

// LoRA projection: P[row][r] = SCALING * dot(in_row, A[e][r][:])
// WHICH: 0 = Pg(x, gate_A), 1 = Pu(x, up_A), 2 = Pd(A2, down_A)
template <int WHICH>
__global__ void proj_kernel(const float* __restrict__ X,
                            const float* __restrict__ Aw) {
    int e = blockIdx.y;
    int cnt = g_counts[e];
    int warp = threadIdx.x >> 5, lane = threadIdx.x & 31;
    int slot = blockIdx.x * 4 + warp;
    if (slot >= cnt) return;
    int grow = g_offsets[e] + slot;
    const float4* w4 = (const float4*)(Aw + (size_t)e * NR * DIM);
    float acc[NR];
#pragma unroll
    for (int r = 0; r < NR; r++) acc[r] = 0.f;

    if (WHICH < 2) {
        const float4* xr = (const float4*)(X + (size_t)g_tok[e*T_TOK + slot] * DIM);
        for (int i = lane; i < DIM/4; i += 32) {
            float4 xv = xr[i];
#pragma unroll
            for (int r = 0; r < NR; r++) {
                float4 a = w4[r * (DIM/4) + i];
                acc[r] += xv.x*a.x + xv.y*a.y + xv.z*a.z + xv.w*a.w;
            }
        }
    } else {
        const __nv_bfloat16* xr = g_A2 + (size_t)grow * DIM;
        for (int i = lane; i < DIM/4; i += 32) {
            uint2 u = *(const uint2*)(xr + (size_t)i * 4);
            __nv_bfloat162 b0 = *reinterpret_cast<__nv_bfloat162*>(&u.x);
            __nv_bfloat162 b1 = *reinterpret_cast<__nv_bfloat162*>(&u.y);
            float2 lo = __bfloat1622float2(b0);
            float2 hi = __bfloat1622float2(b1);
#pragma unroll
            for (int r = 0; r < NR; r++) {
                float4 a = w4[r * (DIM/4) + i];
                acc[r] += lo.x*a.x + lo.y*a.y + hi.x*a.z + hi.y*a.w;
            }
        }
    }
#pragma unroll
    for (int r = 0; r < NR; r++)
#pragma unroll
        for (int o = 16; o > 0; o >>= 1)
            acc[r] += __shfl_xor_sync(0xffffffffu, acc[r], o);
    if (lane < NR) {
        float* P = (WHICH == 0) ? g_Pg : (WHICH == 1) ? g_Pu : g_Pd;
        P[(size_t)grow * NR + lane] = SCALING * acc[lane];
    }
}

// Main expert GEMM. WHICH: 0=gate (x -> g_G), 1=up (x -> silu(G)*u -> g_A2 bf16),
// 2=down (g_A2 -> g_D). K extended by 32 for the LoRA block.
template <int WHICH>
__global__ __launch_bounds__(256, 1)
void gemm_kernel(const float* __restrict__ Xf,
                 const float* __restrict__ W,
                 const float* __restrict__ LB) {
    constexpr int AMODE = (WHICH == 2) ? 1 : 0;   // 0: gather fp32 x, 1: direct bf16 A2
    constexpr int EMODE = (WHICH == 1) ? 1 : 0;   // 1: silu-mul epilogue

    int e = blockIdx.z;
    int cnt = g_counts[e];
    int m0 = blockIdx.y * BM;
    if (m0 >= cnt) return;
    int n0 = blockIdx.x * BN;
    int off = g_offsets[e];
    int tid = threadIdx.x;

    __shared__ __nv_bfloat16 As[2][BM * APAD];
    __shared__ __nv_bfloat16 Bs[2][BN * APAD];
    __shared__ int toks[BM];

    if (AMODE == 0) {
        if (tid < BM)
            toks[tid] = (m0 + tid < cnt) ? g_tok[e*T_TOK + m0 + tid] : -1;
    }
    __syncthreads();

    const float* Pp = (WHICH == 0) ? g_Pg : (WHICH == 1) ? g_Pu : g_Pd;

    uint2 ra[4], rb[4];
    auto loadStage = [&](int s) {
        int k0 = s * BK;
#pragma unroll
        for (int it = 0; it < 4; it++) {
            int idx = tid + it * 256;
            int row = idx >> 3;
            int kl  = (idx & 7) * 4;
            // ---- A operand ----
            if (k0 < DIM) {
                if (AMODE == 0) {
                    int tk = toks[row];
                    if (tk >= 0) {
                        float4 v = *(const float4*)(Xf + (size_t)tk*DIM + k0 + kl);
                        ra[it] = cvt4(v);
                    } else ra[it] = make_uint2(0u, 0u);
                } else {
                    if (m0 + row < cnt)
                        ra[it] = *(const uint2*)(g_A2 + (size_t)(off + m0 + row)*DIM + k0 + kl);
                    else ra[it] = make_uint2(0u, 0u);
                }
            } else {  // LoRA K-extension block
                if (kl < NR && m0 + row < cnt) {
                    float4 v = *(const float4*)(Pp + (size_t)(off + m0 + row)*NR + kl);
                    ra[it] = cvt4(v);
                } else ra[it] = make_uint2(0u, 0u);
            }
            // ---- B operand ----
            if (k0 < DIM) {
                float4 v = *(const float4*)(W + ((size_t)e*DIM + n0 + row)*DIM + k0 + kl);
                rb[it] = cvt4(v);
            } else {
                if (kl < NR) {
                    float4 v = *(const float4*)(LB + ((size_t)e*DIM + n0 + row)*NR + kl);
                    rb[it] = cvt4(v);
                } else rb[it] = make_uint2(0u, 0u);
            }
        }
    };
    auto stsStage = [&](int b) {
#pragma unroll
        for (int it = 0; it < 4; it++) {
            int idx = tid + it * 256;
            int row = idx >> 3;
            int kl  = (idx & 7) * 4;
            *(uint2*)&As[b][row*APAD + kl] = ra[it];
            *(uint2*)&Bs[b][row*APAD + kl] = rb[it];
        }
    };

    float acc[2][8][4];
#pragma unroll
    for (int mt = 0; mt < 2; mt++)
#pragma unroll
        for (int nt = 0; nt < 8; nt++)
#pragma unroll
            for (int i = 0; i < 4; i++) acc[mt][nt][i] = 0.f;

    int lane = tid & 31, warp = tid >> 5;
    int wm = warp & 3, wn = warp >> 2;    // 4 x 2 warp grid; warp tile 32x64
    int g  = lane >> 2, t4 = lane & 3;

    loadStage(0);
    stsStage(0);
    __syncthreads();

    for (int s = 0; s < NST; s++) {
        int cur = s & 1;
        bool more = (s + 1 < NST);
        if (more) loadStage(s + 1);
#pragma unroll
        for (int kk = 0; kk < BK; kk += 16) {
            unsigned af[2][4], bfv[8][2];
#pragma unroll
            for (int mt = 0; mt < 2; mt++) {
                int r = wm*32 + mt*16;
                af[mt][0] = *(const unsigned*)&As[cur][(r+g  )*APAD + kk + 2*t4    ];
                af[mt][1] = *(const unsigned*)&As[cur][(r+g+8)*APAD + kk + 2*t4    ];
                af[mt][2] = *(const unsigned*)&As[cur][(r+g  )*APAD + kk + 2*t4 + 8];
                af[mt][3] = *(const unsigned*)&As[cur][(r+g+8)*APAD + kk + 2*t4 + 8];
            }
#pragma unroll
            for (int nt = 0; nt < 8; nt++) {
                int c = wn*64 + nt*8;
                bfv[nt][0] = *(const unsigned*)&Bs[cur][(c+g)*APAD + kk + 2*t4    ];
                bfv[nt][1] = *(const unsigned*)&Bs[cur][(c+g)*APAD + kk + 2*t4 + 8];
            }
#pragma unroll
            for (int mt = 0; mt < 2; mt++)
#pragma unroll
                for (int nt = 0; nt < 8; nt++)
                    mma16816(acc[mt][nt], af[mt], bfv[nt]);
        }
        if (more) stsStage(cur ^ 1);
        __syncthreads();
    }

    // epilogue
#pragma unroll
    for (int mt = 0; mt < 2; mt++) {
#pragma unroll
        for (int hrow = 0; hrow < 2; hrow++) {
            int r = wm*32 + mt*16 + g + hrow*8;
            if (m0 + r < cnt) {
                size_t grow = (size_t)(off + m0 + r) * DIM;
#pragma unroll
                for (int nt = 0; nt < 8; nt++) {
                    int c = n0 + wn*64 + nt*8 + 2*t4;
                    float v0 = acc[mt][nt][hrow*2 + 0];
                    float v1 = acc[mt][nt][hrow*2 + 1];
                    if (EMODE == 0) {
                        float* dst = (WHICH == 0) ? g_G : g_D;
                        *(float2*)&dst[grow + c] = make_float2(v0, v1);
                    } else {
                        float2 gg = *(const float2*)&g_G[grow + c];
                        float a0 = (gg.x / (1.f + expf(-gg.x))) * v0;
                        float a1 = (gg.y / (1.f + expf(-gg.y))) * v1;
                        __nv_bfloat162 p = __floats2bfloat162_rn(a0, a1);
                        *(unsigned*)&g_A2[grow + c] = *reinterpret_cast<unsigned*>(&p);
                    }
                }
            }
        }
    }
}

// out[t] = hidden[t] + alpha*(g0*D[row0] + g1*D[row1])  (deterministic, no atomics)
__global__ void combine_kernel(const float* __restrict__ Xh,
                               const float* __restrict__ alpha,
                               float* __restrict__ out) {
    int t = blockIdx.x;
    int e0 = g_re[2*t], e1 = g_re[2*t+1];
    size_t r0 = (size_t)(g_offsets[e0] + g_rs[2*t]) * DIM;
    size_t r1 = (size_t)(g_offsets[e1] + g_rs[2*t+1]) * DIM;
    float al = alpha[0];
    float w0 = g_rg[2*t] * al, w1 = g_rg[2*t+1] * al;
    const float4* h4 = (const float4*)(Xh + (size_t)t * DIM);
    const float4* d0 = (const float4*)(g_D + r0);
    const float4* d1 = (const float4*)(g_D + r1);
    float4* o4 = (float4*)(out + (size_t)t * DIM);
    for (int i = threadIdx.x; i < DIM/4; i += blockDim.x) {
        float4 h = h4[i], a = d0[i], b = d1[i], r;
        r.x = h.x + w0*a.x + w1*b.x;
        r.y = h.y + w0*a.y + w1*b.y;
        r.z = h.z + w0*a.z + w1*b.z;
        r.w = h.w + w0*a.w + w1*b.w;
        o4[i] = r;
    }
}

__global__ void loss_kernel(float* __restrict__ out, int idx) {
    if (threadIdx.x == 0) {
        float s = 0.f;
        for (int e = 0; e < NE; e++) s += g_importance[e] * (float)g_counts[e];
        float lb = AUXC * ((float)NE * s / ((float)T_TOK * (float)T_TOK));
        float z  = ZC * (g_zsum / (float)T_TOK);
        out[idx] = lb + z;
    }
}

// ------------------------------- launcher -----------------------------------
extern "C" void kernel_launch(void* const* d_in, const int* in_sizes, int n_in,
                              void* d_out, int out_size) {
    const float* X      = (const float*)d_in[0];
    const float* Wg     = (const float*)d_in[1];
    const float* gate_w = (const float*)d_in[2];
    const float* gate_A = (const float*)d_in[3];
    const float* gate_B = (const float*)d_in[4];
    const float* up_w   = (const float*)d_in[5];
    const float* up_A   = (const float*)d_in[6];
    const float* up_B   = (const float*)d_in[7];
    const float* down_w = (const float*)d_in[8];
    const float* down_A = (const float*)d_in[9];
    const float* down_B = (const float*)d_in[10];
    const float* alpha  = (const float*)d_in[11];
    float* out = (float*)d_out;

    init_kernel<<<1, 32>>>();
    router_kernel<<<T_TOK/8, 256>>>(X, Wg);
    offsets_kernel<<<1, 1>>>();

    dim3 pgrid(T_TOK/4, NE);
    proj_kernel<0><<<pgrid, 128>>>(X, gate_A);
    proj_kernel<1><<<pgrid, 128>>>(X, up_A);

    dim3 ggrid(DIM/BN, T_TOK/BM, NE);
    gemm_kernel<0><<<ggrid, 256>>>(X, gate_w, gate_B);   // g -> g_G
    gemm_kernel<1><<<ggrid, 256>>>(X, up_w, up_B);       // silu(g)*u -> g_A2

    proj_kernel<2><<<pgrid, 128>>>(X, down_A);
    gemm_kernel<2><<<ggrid, 256>>>(X, down_w, down_B);   // -> g_D

    combine_kernel<<<T_TOK, 256>>>(X, alpha, out);
    loss_kernel<<<1, 1>>>(out, out_size - 1);
}

// round 3
// speedup vs baseline: 1.5723x; 1.5723x over previous
#include <cuda_runtime.h>
#include <cuda_bf16.h>
#include <math.h>
#include <stdint.h>

// ---------------------------------------------------------------------------
// MoE + LoRA forward, routed sparsely (top-2 of 8 experts), bf16 tensor cores.
// Round 2: bf16 preconversion + cp.async 3-stage pipeline + ldmatrix frags.
// ---------------------------------------------------------------------------

#define DIM    2048
#define T_TOK  8192
#define NE     8
#define NR     16
#define NROWS  (T_TOK*2)
#define SCALING 2.0f
#define AUXC   0.01f
#define ZC     0.001f

#define BM 128
#define BN 128
#define BK 64
#define NSTAGES (DIM/BK + 1)       // 33: 32 main K stages + 1 LoRA ext stage
#define STG_HALVES (128*64)        // one 128x64-half tile
#define GSMEM (3*STG_HALVES*2*2 + 512)   // As[3]+Bs[3] bf16 + toks

// ------------------------- scratch (device globals) ------------------------
__device__ int   g_counts[NE];
__device__ int   g_offsets[NE+1];
__device__ float g_importance[NE];
__device__ float g_zsum;
__device__ int   g_tok[NE*T_TOK];
__device__ int   g_re[NROWS];
__device__ int   g_rs[NROWS];
__device__ float g_rg[NROWS];

__device__ __nv_bfloat16 g_Xb[(size_t)T_TOK*DIM];          // bf16 copy of X
__device__ __nv_bfloat16 g_Wgb[(size_t)NE*DIM*DIM];        // bf16 weights
__device__ __nv_bfloat16 g_Wub[(size_t)NE*DIM*DIM];
__device__ __nv_bfloat16 g_Wdb[(size_t)NE*DIM*DIM];
__device__ __nv_bfloat16 g_LBg[(size_t)NE*DIM*64];         // LoRA B, padded to 64
__device__ __nv_bfloat16 g_LBu[(size_t)NE*DIM*64];
__device__ __nv_bfloat16 g_LBd[(size_t)NE*DIM*64];
__device__ __nv_bfloat16 g_Pg[(size_t)NROWS*64];           // LoRA proj, padded 64
__device__ __nv_bfloat16 g_Pu[(size_t)NROWS*64];
__device__ __nv_bfloat16 g_Pd[(size_t)NROWS*64];

__device__ float g_G[(size_t)NROWS*DIM];                   // gate pre-act
__device__ __nv_bfloat16 g_A2[(size_t)NROWS*DIM];          // silu(g)*u
__device__ float g_D[(size_t)NROWS*DIM];                   // down output

// ------------------------------- helpers -----------------------------------
__device__ __forceinline__ uint2 cvt4(float4 v) {
    __nv_bfloat162 lo = __floats2bfloat162_rn(v.x, v.y);
    __nv_bfloat162 hi = __floats2bfloat162_rn(v.z, v.w);
    uint2 r;
    r.x = *reinterpret_cast<unsigned*>(&lo);
    r.y = *reinterpret_cast<unsigned*>(&hi);
    return r;
}

__device__ __forceinline__ void mma16816(float* d, const unsigned* a, const unsigned* b) {
    asm volatile(
        "mma.sync.aligned.m16n8k16.row.col.f32.bf16.bf16.f32 "
        "{%0,%1,%2,%3}, {%4,%5,%6,%7}, {%8,%9}, {%0,%1,%2,%3};\n"
        : "+f"(d[0]), "+f"(d[1]), "+f"(d[2]), "+f"(d[3])
        : "r"(a[0]), "r"(a[1]), "r"(a[2]), "r"(a[3]), "r"(b[0]), "r"(b[1]));
}

__device__ __forceinline__ void ldsm4(unsigned &r0, unsigned &r1, unsigned &r2,
                                      unsigned &r3, uint32_t addr) {
    asm volatile("ldmatrix.sync.aligned.m8n8.x4.shared.b16 {%0,%1,%2,%3}, [%4];\n"
                 : "=r"(r0), "=r"(r1), "=r"(r2), "=r"(r3) : "r"(addr));
}

__device__ __forceinline__ void cpa16(uint32_t dst, const void* src, int sz) {
    asm volatile("cp.async.cg.shared.global [%0], [%1], 16, %2;\n"
                 :: "r"(dst), "l"(src), "r"(sz));
}
#define CP_COMMIT asm volatile("cp.async.commit_group;\n")
template<int N> __device__ __forceinline__ void cp_wait() {
    asm volatile("cp.async.wait_group %0;\n" :: "n"(N));
}

// --------------------------- prep (fp32 -> bf16) ----------------------------
__global__ void f2b_kernel(const float4* __restrict__ src, uint2* __restrict__ dst, int n4) {
    int i = blockIdx.x * blockDim.x + threadIdx.x;
    if (i < n4) dst[i] = cvt4(src[i]);
}
// LoRA B: [rows][16] fp32 -> [rows][64] bf16 (upper 48 zero)
__global__ void lbpad_kernel(const float* __restrict__ src, __nv_bfloat16* __restrict__ dst) {
    int i = blockIdx.x * blockDim.x + threadIdx.x;   // rows*64 total
    int row = i >> 6, col = i & 63;
    dst[i] = (col < NR) ? __float2bfloat16(src[row*NR + col]) : __float2bfloat16(0.f);
}

// ------------------------------- routing ------------------------------------
__global__ void init_kernel() {
    int t = threadIdx.x;
    if (t < NE) { g_counts[t] = 0; g_importance[t] = 0.f; }
    if (t == 0) g_zsum = 0.f;
}

__global__ void router_kernel(const float* __restrict__ X,
                              const float* __restrict__ Wg) {
    int warp = threadIdx.x >> 5, lane = threadIdx.x & 31;
    int t = blockIdx.x * 8 + warp;
    if (t >= T_TOK) return;
    const float4* xr = (const float4*)(X + (size_t)t * DIM);
    float acc[NE];
#pragma unroll
    for (int e = 0; e < NE; e++) acc[e] = 0.f;
    for (int i = lane; i < DIM/4; i += 32) {
        float4 xv = xr[i];
#pragma unroll
        for (int e = 0; e < NE; e++) {
            float4 w = ((const float4*)(Wg + (size_t)e * DIM))[i];
            acc[e] += xv.x*w.x + xv.y*w.y + xv.z*w.z + xv.w*w.w;
        }
    }
#pragma unroll
    for (int e = 0; e < NE; e++)
#pragma unroll
        for (int o = 16; o > 0; o >>= 1)
            acc[e] += __shfl_xor_sync(0xffffffffu, acc[e], o);

    if (lane == 0) {
        int e0 = 0;
#pragma unroll
        for (int e = 1; e < NE; e++) if (acc[e] > acc[e0]) e0 = e;
        int e1 = (e0 == 0) ? 1 : 0;
#pragma unroll
        for (int e = 0; e < NE; e++)
            if (e != e0 && acc[e] > acc[e1]) e1 = e;

        float m = acc[e0];
        float s = 0.f;
#pragma unroll
        for (int e = 0; e < NE; e++) s += expf(acc[e] - m);
        float lse = logf(s) + m;
        atomicAdd(&g_zsum, lse * lse);

        float d = expf(acc[e1] - acc[e0]);
        float p0 = 1.f / (1.f + d);
        float p1 = d / (1.f + d);

        int s0 = atomicAdd(&g_counts[e0], 1);
        int s1 = atomicAdd(&g_counts[e1], 1);
        g_tok[e0*T_TOK + s0] = t;
        g_tok[e1*T_TOK + s1] = t;
        atomicAdd(&g_importance[e0], p0);
        atomicAdd(&g_importance[e1], p1);
        g_re[2*t] = e0;  g_rs[2*t] = s0;  g_rg[2*t] = p0;
        g_re[2*t+1] = e1; g_rs[2*t+1] = s1; g_rg[2*t+1] = p1;
    }
}

__global__ void offsets_kernel() {
    if (threadIdx.x == 0) {
        int o = 0;
        for (int e = 0; e < NE; e++) { g_offsets[e] = o; o += g_counts[e]; }
        g_offsets[NE] = o;
    }
}

// ------------------- LoRA projections (gate+up fused; down) -----------------
// Pg/Pu[grow][r] = SCALING * dot(X[tok], A[e][r]); bf16 padded to 64.
__global__ __launch_bounds__(256, 2)
void proj_gu_kernel(const float* __restrict__ gA, const float* __restrict__ uA) {
    int e = blockIdx.y;
    int cnt = g_counts[e];
    int s0 = blockIdx.x * 64;
    if (s0 >= cnt) return;
    int off = g_offsets[e];
    __shared__ __nv_bfloat16 Xs[64][128];
    __shared__ float Asm[32][128];
    __shared__ int toks[64];
    int tid = threadIdx.x;
    if (tid < 64) toks[tid] = (s0 + tid < cnt) ? g_tok[e*T_TOK + s0 + tid] : 0;
    __syncthreads();
    int lr = tid >> 2, q = tid & 3;
    float acc[8];
#pragma unroll
    for (int j = 0; j < 8; j++) acc[j] = 0.f;

    for (int c = 0; c < 16; c++) {
        int k0 = c * 128;
#pragma unroll
        for (int i = 0; i < 16; i++) {
            int idx = tid + i * 256;       // 4096 = 32 rows * 128
            int r = idx >> 7, k = idx & 127;
            Asm[r][k] = (r < NR) ? gA[((size_t)e*NR + r)*DIM + k0 + k]
                                 : uA[((size_t)e*NR + (r-NR))*DIM + k0 + k];
        }
#pragma unroll
        for (int i = 0; i < 4; i++) {
            int idx = tid + i * 256;       // 1024 chunks of 8 halves
            int r = idx >> 4, kc = (idx & 15) * 8;
            *(uint4*)&Xs[r][kc] = *(const uint4*)(g_Xb + (size_t)toks[r]*DIM + k0 + kc);
        }
        __syncthreads();
        for (int k = 0; k < 128; k += 2) {
            float2 xf = __bfloat1622float2(*(__nv_bfloat162*)&Xs[lr][k]);
#pragma unroll
            for (int j = 0; j < 8; j++) {
                float2 af = *(float2*)&Asm[q*8 + j][k];
                acc[j] += xf.x*af.x + xf.y*af.y;
            }
        }
        __syncthreads();
    }
    if (s0 + lr < cnt) {
        size_t grow = (size_t)(off + s0 + lr);
        __nv_bfloat16* dstP = (q < 2) ? g_Pg : g_Pu;
        int base = (q & 1) * 8;
#pragma unroll
        for (int j = 0; j < 8; j++)
            dstP[grow*64 + base + j] = __float2bfloat16(SCALING * acc[j]);
        int zb = 16 + (q & 1) * 24;
#pragma unroll
        for (int j = 0; j < 24; j++)
            dstP[grow*64 + zb + j] = __float2bfloat16(0.f);
    }
}

// Pd[grow][r] = SCALING * dot(A2[grow], down_A[e][r])
__global__ __launch_bounds__(256, 2)
void proj_d_kernel(const float* __restrict__ dA) {
    int e = blockIdx.y;
    int cnt = g_counts[e];
    int s0 = blockIdx.x * 128;
    if (s0 >= cnt) return;
    int off = g_offsets[e];
    __shared__ __nv_bfloat16 Xs[128][128];
    __shared__ float Asm[16][128];
    int tid = threadIdx.x;
    int lr = tid >> 1, q = tid & 1;
    float acc[8];
#pragma unroll
    for (int j = 0; j < 8; j++) acc[j] = 0.f;

    for (int c = 0; c < 16; c++) {
        int k0 = c * 128;
#pragma unroll
        for (int i = 0; i < 8; i++) {
            int idx = tid + i * 256;       // 2048 = 16 rows * 128
            int r = idx >> 7, k = idx & 127;
            Asm[r][k] = dA[((size_t)e*NR + r)*DIM + k0 + k];
        }
#pragma unroll
        for (int i = 0; i < 8; i++) {
            int idx = tid + i * 256;       // 2048 chunks of 8 halves
            int r = idx >> 4, kc = (idx & 15) * 8;
            int rr = (s0 + r < cnt) ? (s0 + r) : (cnt - 1);
            *(uint4*)&Xs[r][kc] = *(const uint4*)(g_A2 + (size_t)(off + rr)*DIM + k0 + kc);
        }
        __syncthreads();
        for (int k = 0; k < 128; k += 2) {
            float2 xf = __bfloat1622float2(*(__nv_bfloat162*)&Xs[lr][k]);
#pragma unroll
            for (int j = 0; j < 8; j++) {
                float2 af = *(float2*)&Asm[q*8 + j][k];
                acc[j] += xf.x*af.x + xf.y*af.y;
            }
        }
        __syncthreads();
    }
    if (s0 + lr < cnt) {
        size_t grow = (size_t)(off + s0 + lr);
#pragma unroll
        for (int j = 0; j < 8; j++)
            g_Pd[grow*64 + q*8 + j] = __float2bfloat16(SCALING * acc[j]);
        int zb = 16 + q * 24;
#pragma unroll
        for (int j = 0; j < 24; j++)
            g_Pd[grow*64 + zb + j] = __float2bfloat16(0.f);
    }
}

// ------------------------------- main GEMMs ---------------------------------
// WHICH 0: gate  (A = gathered Xb)        -> g_G (fp32)
// WHICH 1: up    (A = gathered Xb)        -> silu(g_G)*u -> g_A2 (bf16)
// WHICH 2: down  (A = g_A2 rows, direct)  -> g_D (fp32)
template <int WHICH>
__global__ __launch_bounds__(256, 1)
void gemm_kernel() {
    int e = blockIdx.z;
    int cnt = g_counts[e];
    int m0 = blockIdx.y * BM;
    if (m0 >= cnt) return;
    int n0 = blockIdx.x * BN;
    int off = g_offsets[e];
    int tid = threadIdx.x;

    extern __shared__ char smem_raw[];
    __nv_bfloat16* As = (__nv_bfloat16*)smem_raw;
    __nv_bfloat16* Bs = As + 3*STG_HALVES;
    int* toks = (int*)(Bs + 3*STG_HALVES);

    const __nv_bfloat16* Wb  = (WHICH == 0) ? g_Wgb : (WHICH == 1) ? g_Wub : g_Wdb;
    const __nv_bfloat16* Pb  = (WHICH == 0) ? g_Pg  : (WHICH == 1) ? g_Pu  : g_Pd;
    const __nv_bfloat16* LBb = (WHICH == 0) ? g_LBg : (WHICH == 1) ? g_LBu : g_LBd;

    if (WHICH < 2) {
        if (tid < BM)
            toks[tid] = (m0 + tid < cnt) ? g_tok[e*T_TOK + m0 + tid] : -1;
    }
    __syncthreads();

    uint32_t smA = (uint32_t)__cvta_generic_to_shared(As);
    uint32_t smB = (uint32_t)__cvta_generic_to_shared(Bs);

    auto loadStage = [&](int s) {
        int buf = (s % 3) * STG_HALVES;
        int k0 = s * BK;
        bool ext = (s == NSTAGES - 1);
#pragma unroll
        for (int it = 0; it < 4; it++) {           // A: 1024 chunks of 16B
            int c = tid + it * 256;
            int row = c >> 3, ch = c & 7;
            uint32_t dst = smA + (uint32_t)(buf + row*64 + ((ch ^ (row & 7)) * 8)) * 2;
            const __nv_bfloat16* src;
            int sz = 16;
            if (!ext) {
                if (WHICH < 2) {
                    int tk = toks[row];
                    if (tk < 0) { sz = 0; tk = 0; }
                    src = g_Xb + (size_t)tk*DIM + k0 + ch*8;
                } else {
                    int r = m0 + row;
                    bool v = r < cnt;
                    src = g_A2 + (size_t)(off + (v ? r : 0))*DIM + k0 + ch*8;
                    sz = v ? 16 : 0;
                }
            } else {
                int r = m0 + row;
                bool v = r < cnt;
                src = Pb + (size_t)(off + (v ? r : 0))*64 + ch*8;
                sz = v ? 16 : 0;
            }
            cpa16(dst, src, sz);
        }
#pragma unroll
        for (int it = 0; it < 4; it++) {           // B
            int c = tid + it * 256;
            int row = c >> 3, ch = c & 7;
            uint32_t dst = smB + (uint32_t)(buf + row*64 + ((ch ^ (row & 7)) * 8)) * 2;
            const __nv_bfloat16* src = ext
                ? LBb + ((size_t)e*DIM + n0 + row)*64 + ch*8
                : Wb  + ((size_t)e*DIM + n0 + row)*DIM + k0 + ch*8;
            cpa16(dst, src, 16);
        }
    };

    float acc[2][8][4];
#pragma unroll
    for (int mt = 0; mt < 2; mt++)
#pragma unroll
        for (int nt = 0; nt < 8; nt++)
#pragma unroll
            for (int i = 0; i < 4; i++) acc[mt][nt][i] = 0.f;

    int lane = tid & 31, warp = tid >> 5;
    int wm = warp & 3, wn = warp >> 2;    // warp tile 32 x 64
    int g  = lane >> 2, t4 = lane & 3;

    loadStage(0); CP_COMMIT;
    loadStage(1); CP_COMMIT;

    for (int s = 0; s < NSTAGES; s++) {
        cp_wait<1>();
        __syncthreads();
        if (s + 2 < NSTAGES) loadStage(s + 2);
        CP_COMMIT;

        int buf = (s % 3) * STG_HALVES;
#pragma unroll
        for (int kk = 0; kk < BK; kk += 16) {
            int kh = kk + ((lane >> 4) << 3);
            unsigned af[2][4];
#pragma unroll
            for (int mt = 0; mt < 2; mt++) {
                int arow = wm*32 + mt*16 + (lane & 15);
                uint32_t a = smA + (uint32_t)(buf + arow*64 +
                              (((kh >> 3) ^ (arow & 7)) << 3)) * 2;
                ldsm4(af[mt][0], af[mt][1], af[mt][2], af[mt][3], a);
            }
            unsigned bq[8][2];
#pragma unroll
            for (int p = 0; p < 4; p++) {
                int brow = wn*64 + p*16 + (lane & 15);
                uint32_t b = smB + (uint32_t)(buf + brow*64 +
                              (((kh >> 3) ^ (brow & 7)) << 3)) * 2;
                unsigned q0, q1, q2, q3;
                ldsm4(q0, q1, q2, q3, b);
                bq[2*p][0]   = q0; bq[2*p][1]   = q2;
                bq[2*p+1][0] = q1; bq[2*p+1][1] = q3;
            }
#pragma unroll
            for (int mt = 0; mt < 2; mt++)
#pragma unroll
                for (int nt = 0; nt < 8; nt++)
                    mma16816(acc[mt][nt], af[mt], bq[nt]);
        }
    }

    // epilogue
#pragma unroll
    for (int mt = 0; mt < 2; mt++) {
#pragma unroll
        for (int hrow = 0; hrow < 2; hrow++) {
            int r = wm*32 + mt*16 + g + hrow*8;
            if (m0 + r < cnt) {
                size_t grow = (size_t)(off + m0 + r) * DIM;
#pragma unroll
                for (int nt = 0; nt < 8; nt++) {
                    int c = n0 + wn*64 + nt*8 + 2*t4;
                    float v0 = acc[mt][nt][hrow*2 + 0];
                    float v1 = acc[mt][nt][hrow*2 + 1];
                    if (WHICH == 0) {
                        *(float2*)&g_G[grow + c] = make_float2(v0, v1);
                    } else if (WHICH == 2) {
                        *(float2*)&g_D[grow + c] = make_float2(v0, v1);
                    } else {
                        float2 gg = *(const float2*)&g_G[grow + c];
                        float a0 = (gg.x / (1.f + expf(-gg.x))) * v0;
                        float a1 = (gg.y / (1.f + expf(-gg.y))) * v1;
                        __nv_bfloat162 p = __floats2bfloat162_rn(a0, a1);
                        *(unsigned*)&g_A2[grow + c] = *reinterpret_cast<unsigned*>(&p);
                    }
                }
            }
        }
    }
}

// --------------------------- combine + loss ---------------------------------
__global__ void combine_kernel(const float* __restrict__ Xh,
                               const float* __restrict__ alpha,
                               float* __restrict__ out) {
    int t = blockIdx.x;
    int e0 = g_re[2*t], e1 = g_re[2*t+1];
    size_t r0 = (size_t)(g_offsets[e0] + g_rs[2*t]) * DIM;
    size_t r1 = (size_t)(g_offsets[e1] + g_rs[2*t+1]) * DIM;
    float al = alpha[0];
    float w0 = g_rg[2*t] * al, w1 = g_rg[2*t+1] * al;
    const float4* h4 = (const float4*)(Xh + (size_t)t * DIM);
    const float4* d0 = (const float4*)(g_D + r0);
    const float4* d1 = (const float4*)(g_D + r1);
    float4* o4 = (float4*)(out + (size_t)t * DIM);
    for (int i = threadIdx.x; i < DIM/4; i += blockDim.x) {
        float4 h = h4[i], a = d0[i], b = d1[i], r;
        r.x = h.x + w0*a.x + w1*b.x;
        r.y = h.y + w0*a.y + w1*b.y;
        r.z = h.z + w0*a.z + w1*b.z;
        r.w = h.w + w0*a.w + w1*b.w;
        o4[i] = r;
    }
}

__global__ void loss_kernel(float* __restrict__ out, int idx) {
    if (threadIdx.x == 0) {
        float s = 0.f;
        for (int e = 0; e < NE; e++) s += g_importance[e] * (float)g_counts[e];
        float lb = AUXC * ((float)NE * s / ((float)T_TOK * (float)T_TOK));
        float z  = ZC * (g_zsum / (float)T_TOK);
        out[idx] = lb + z;
    }
}

// ------------------------------- launcher -----------------------------------
extern "C" void kernel_launch(void* const* d_in, const int* in_sizes, int n_in,
                              void* d_out, int out_size) {
    const float* X      = (const float*)d_in[0];
    const float* Wg     = (const float*)d_in[1];
    const float* gate_w = (const float*)d_in[2];
    const float* gate_A = (const float*)d_in[3];
    const float* gate_B = (const float*)d_in[4];
    const float* up_w   = (const float*)d_in[5];
    const float* up_A   = (const float*)d_in[6];
    const float* up_B   = (const float*)d_in[7];
    const float* down_w = (const float*)d_in[8];
    const float* down_A = (const float*)d_in[9];
    const float* down_B = (const float*)d_in[10];
    const float* alpha  = (const float*)d_in[11];
    float* out = (float*)d_out;

    cudaFuncSetAttribute(gemm_kernel<0>, cudaFuncAttributeMaxDynamicSharedMemorySize, GSMEM);
    cudaFuncSetAttribute(gemm_kernel<1>, cudaFuncAttributeMaxDynamicSharedMemorySize, GSMEM);
    cudaFuncSetAttribute(gemm_kernel<2>, cudaFuncAttributeMaxDynamicSharedMemorySize, GSMEM);

    // fp32 -> bf16 preconversion
    __nv_bfloat16 *dXb, *dWgb, *dWub, *dWdb, *dLBg, *dLBu, *dLBd;
    cudaGetSymbolAddress((void**)&dXb,  g_Xb);
    cudaGetSymbolAddress((void**)&dWgb, g_Wgb);
    cudaGetSymbolAddress((void**)&dWub, g_Wub);
    cudaGetSymbolAddress((void**)&dWdb, g_Wdb);
    cudaGetSymbolAddress((void**)&dLBg, g_LBg);
    cudaGetSymbolAddress((void**)&dLBu, g_LBu);
    cudaGetSymbolAddress((void**)&dLBd, g_LBd);

    int n4X = T_TOK*DIM/4;
    int n4W = NE*DIM*DIM/4;
    f2b_kernel<<<(n4X+255)/256, 256>>>((const float4*)X, (uint2*)dXb, n4X);
    f2b_kernel<<<(n4W+255)/256, 256>>>((const float4*)gate_w, (uint2*)dWgb, n4W);
    f2b_kernel<<<(n4W+255)/256, 256>>>((const float4*)up_w,   (uint2*)dWub, n4W);
    f2b_kernel<<<(n4W+255)/256, 256>>>((const float4*)down_w, (uint2*)dWdb, n4W);
    int nLB = NE*DIM*64;
    lbpad_kernel<<<(nLB+255)/256, 256>>>(gate_B, dLBg);
    lbpad_kernel<<<(nLB+255)/256, 256>>>(up_B,   dLBu);
    lbpad_kernel<<<(nLB+255)/256, 256>>>(down_B, dLBd);

    init_kernel<<<1, 32>>>();
    router_kernel<<<T_TOK/8, 256>>>(X, Wg);
    offsets_kernel<<<1, 1>>>();

    dim3 pg(T_TOK/64, NE);
    proj_gu_kernel<<<pg, 256>>>(gate_A, up_A);

    dim3 ggrid(DIM/BN, T_TOK/BM, NE);
    gemm_kernel<0><<<ggrid, 256, GSMEM>>>();
    gemm_kernel<1><<<ggrid, 256, GSMEM>>>();

    dim3 pd(T_TOK/128, NE);
    proj_d_kernel<<<pd, 256>>>(down_A);
    gemm_kernel<2><<<ggrid, 256, GSMEM>>>();

    combine_kernel<<<T_TOK, 256>>>(X, alpha, out);
    loss_kernel<<<1, 1>>>(out, out_size - 1);
}

// round 6
// speedup vs baseline: 1.9484x; 1.2392x over previous
#include <cuda_runtime.h>
#include <cuda_bf16.h>
#include <math.h>
#include <stdint.h>

// ---------------------------------------------------------------------------
// MoE + LoRA forward, routed top-2/8. Legacy mma.sync bf16 tensor path
// (tcgen05 unavailable: build targets plain sm_103 PTX).
// Round 6: dense-gathered padded rows, fused gate+up GEMM (shared A tile,
// silu epilogue from registers), 2 CTAs/SM, cp.async 3-slot ring + ldmatrix.
// ---------------------------------------------------------------------------

#define DIM    2048
#define T_TOK  8192
#define NE     8
#define NR     16
#define NROWS  (T_TOK*2)
#define PADROWS (NROWS + NE*128)      // per-expert counts padded to 128
#define MAXTILES (PADROWS/128)        // 136
#define SCALING 2.0f
#define AUXC   0.01f
#define ZC     0.001f

#define BK 64
#define GU_STG (128*64 + 64*64 + 64*64)   // halves per stage: A + Bg + Bu
#define D_STG  (128*64 + 128*64)          // halves per stage: A + B
#define GU_SMEM (3*GU_STG*2)              // 98304 B
#define D_SMEM  (3*D_STG*2)               // 98304 B

// ------------------------- scratch (device globals) ------------------------
__device__ int   g_counts[NE];
__device__ int   g_offsets[NE+1];     // padded cumulative offsets
__device__ int   g_tile_e[MAXTILES];
__device__ int   g_ntiles;
__device__ float g_importance[NE];
__device__ float g_zsum;
__device__ int   g_tok[NE*T_TOK];
__device__ int   g_re[NROWS];
__device__ int   g_rs[NROWS];
__device__ float g_rg[NROWS];

__device__ __nv_bfloat16 g_Xg[(size_t)PADROWS*DIM];    // gathered bf16 X rows
__device__ __nv_bfloat16 g_Wgb[(size_t)NE*DIM*DIM];    // bf16 weights
__device__ __nv_bfloat16 g_Wub[(size_t)NE*DIM*DIM];
__device__ __nv_bfloat16 g_Wdb[(size_t)NE*DIM*DIM];
__device__ __nv_bfloat16 g_LBg[(size_t)NE*DIM*64];     // LoRA B padded to 64
__device__ __nv_bfloat16 g_LBu[(size_t)NE*DIM*64];
__device__ __nv_bfloat16 g_LBd[(size_t)NE*DIM*64];
__device__ __nv_bfloat16 g_Pg[(size_t)PADROWS*64];     // LoRA projections
__device__ __nv_bfloat16 g_Pu[(size_t)PADROWS*64];     // (pad rows stay zero)
__device__ __nv_bfloat16 g_Pd[(size_t)PADROWS*64];

__device__ __nv_bfloat16 g_A2[(size_t)PADROWS*DIM];    // silu(g)*u
__device__ float g_D[(size_t)PADROWS*DIM];             // down output

// ------------------------------- helpers -----------------------------------
__device__ __forceinline__ uint2 cvt4(float4 v) {
    __nv_bfloat162 lo = __floats2bfloat162_rn(v.x, v.y);
    __nv_bfloat162 hi = __floats2bfloat162_rn(v.z, v.w);
    uint2 r;
    r.x = *reinterpret_cast<unsigned*>(&lo);
    r.y = *reinterpret_cast<unsigned*>(&hi);
    return r;
}

__device__ __forceinline__ void mma16816(float* d, const unsigned* a, const unsigned* b) {
    asm volatile(
        "mma.sync.aligned.m16n8k16.row.col.f32.bf16.bf16.f32 "
        "{%0,%1,%2,%3}, {%4,%5,%6,%7}, {%8,%9}, {%0,%1,%2,%3};\n"
        : "+f"(d[0]), "+f"(d[1]), "+f"(d[2]), "+f"(d[3])
        : "r"(a[0]), "r"(a[1]), "r"(a[2]), "r"(a[3]), "r"(b[0]), "r"(b[1]));
}

__device__ __forceinline__ void ldsm4(unsigned &r0, unsigned &r1, unsigned &r2,
                                      unsigned &r3, uint32_t addr) {
    asm volatile("ldmatrix.sync.aligned.m8n8.x4.shared.b16 {%0,%1,%2,%3}, [%4];\n"
                 : "=r"(r0), "=r"(r1), "=r"(r2), "=r"(r3) : "r"(addr));
}

__device__ __forceinline__ void cpa16(uint32_t dst, const void* src) {
    asm volatile("cp.async.cg.shared.global [%0], [%1], 16;\n" :: "r"(dst), "l"(src));
}
#define CP_COMMIT asm volatile("cp.async.commit_group;\n")
template<int N> __device__ __forceinline__ void cp_wait() {
    asm volatile("cp.async.wait_group %0;\n" :: "n"(N));
}

// --------------------------- prep (fp32 -> bf16) ----------------------------
__global__ void f2b_kernel(const float4* __restrict__ src, uint2* __restrict__ dst, int n4) {
    int i = blockIdx.x * blockDim.x + threadIdx.x;
    if (i < n4) dst[i] = cvt4(src[i]);
}
__global__ void lbpad_kernel(const float* __restrict__ src, __nv_bfloat16* __restrict__ dst) {
    int i = blockIdx.x * blockDim.x + threadIdx.x;
    int row = i >> 6, col = i & 63;
    dst[i] = (col < NR) ? __float2bfloat16(src[row*NR + col]) : __float2bfloat16(0.f);
}

// ------------------------------- routing ------------------------------------
__global__ void init_kernel() {
    int t = threadIdx.x;
    if (t < NE) { g_counts[t] = 0; g_importance[t] = 0.f; }
    if (t == 0) g_zsum = 0.f;
}

__global__ void router_kernel(const float* __restrict__ X,
                              const float* __restrict__ Wg) {
    int warp = threadIdx.x >> 5, lane = threadIdx.x & 31;
    int t = blockIdx.x * 8 + warp;
    if (t >= T_TOK) return;
    const float4* xr = (const float4*)(X + (size_t)t * DIM);
    float acc[NE];
#pragma unroll
    for (int e = 0; e < NE; e++) acc[e] = 0.f;
    for (int i = lane; i < DIM/4; i += 32) {
        float4 xv = xr[i];
#pragma unroll
        for (int e = 0; e < NE; e++) {
            float4 w = ((const float4*)(Wg + (size_t)e * DIM))[i];
            acc[e] += xv.x*w.x + xv.y*w.y + xv.z*w.z + xv.w*w.w;
        }
    }
#pragma unroll
    for (int e = 0; e < NE; e++)
#pragma unroll
        for (int o = 16; o > 0; o >>= 1)
            acc[e] += __shfl_xor_sync(0xffffffffu, acc[e], o);

    if (lane == 0) {
        int e0 = 0;
#pragma unroll
        for (int e = 1; e < NE; e++) if (acc[e] > acc[e0]) e0 = e;
        int e1 = (e0 == 0) ? 1 : 0;
#pragma unroll
        for (int e = 0; e < NE; e++)
            if (e != e0 && acc[e] > acc[e1]) e1 = e;

        float m = acc[e0];
        float s = 0.f;
#pragma unroll
        for (int e = 0; e < NE; e++) s += expf(acc[e] - m);
        float lse = logf(s) + m;
        atomicAdd(&g_zsum, lse * lse);

        float d = expf(acc[e1] - acc[e0]);
        float p0 = 1.f / (1.f + d);
        float p1 = d / (1.f + d);

        int s0 = atomicAdd(&g_counts[e0], 1);
        int s1 = atomicAdd(&g_counts[e1], 1);
        g_tok[e0*T_TOK + s0] = t;
        g_tok[e1*T_TOK + s1] = t;
        atomicAdd(&g_importance[e0], p0);
        atomicAdd(&g_importance[e1], p1);
        g_re[2*t] = e0;  g_rs[2*t] = s0;  g_rg[2*t] = p0;
        g_re[2*t+1] = e1; g_rs[2*t+1] = s1; g_rg[2*t+1] = p1;
    }
}

__global__ void offsets_kernel() {
    if (threadIdx.x == 0) {
        int o = 0;
        for (int e = 0; e < NE; e++) {
            g_offsets[e] = o;
            int pt = (g_counts[e] + 127) >> 7;
            for (int i = 0; i < pt; i++) g_tile_e[(o >> 7) + i] = e;
            o += pt << 7;
        }
        g_offsets[NE] = o;
        g_ntiles = o >> 7;
    }
}

// gather: Xg[row] = bf16(X[tok(row)]) for real slots, zeros for pad slots
__global__ void gather_kernel(const float* __restrict__ X) {
    int row = blockIdx.x;
    if (row >= g_offsets[NE]) return;
    int e = g_tile_e[row >> 7];
    int slot = row - g_offsets[e];
    __nv_bfloat16* dst = g_Xg + (size_t)row * DIM;
    if (slot < g_counts[e]) {
        const float4* src = (const float4*)(X + (size_t)g_tok[e*T_TOK + slot] * DIM);
        for (int i = threadIdx.x; i < DIM/4; i += blockDim.x)
            *(uint2*)(dst + i*4) = cvt4(src[i]);
    } else {
        for (int i = threadIdx.x; i < DIM/4; i += blockDim.x)
            *(uint2*)(dst + i*4) = make_uint2(0u, 0u);
    }
}

// ------------------- LoRA projections (gate+up fused; down) -----------------
__global__ __launch_bounds__(256, 2)
void proj_gu_kernel(const float* __restrict__ gA, const float* __restrict__ uA) {
    int e = blockIdx.y;
    int cnt = g_counts[e];
    int s0 = blockIdx.x * 64;
    if (s0 >= cnt) return;
    int off = g_offsets[e];
    __shared__ __nv_bfloat16 Xs[64][128];
    __shared__ float Asm[32][128];
    int tid = threadIdx.x;
    int lr = tid >> 2, q = tid & 3;
    float acc[8];
#pragma unroll
    for (int j = 0; j < 8; j++) acc[j] = 0.f;

    for (int c = 0; c < 16; c++) {
        int k0 = c * 128;
#pragma unroll
        for (int i = 0; i < 16; i++) {
            int idx = tid + i * 256;
            int r = idx >> 7, k = idx & 127;
            Asm[r][k] = (r < NR) ? gA[((size_t)e*NR + r)*DIM + k0 + k]
                                 : uA[((size_t)e*NR + (r-NR))*DIM + k0 + k];
        }
#pragma unroll
        for (int i = 0; i < 4; i++) {
            int idx = tid + i * 256;
            int r = idx >> 4, kc = (idx & 15) * 8;
            *(uint4*)&Xs[r][kc] = *(const uint4*)(g_Xg + (size_t)(off + s0 + r)*DIM + k0 + kc);
        }
        __syncthreads();
        for (int k = 0; k < 128; k += 2) {
            float2 xf = __bfloat1622float2(*(__nv_bfloat162*)&Xs[lr][k]);
#pragma unroll
            for (int j = 0; j < 8; j++) {
                float2 af = *(float2*)&Asm[q*8 + j][k];
                acc[j] += xf.x*af.x + xf.y*af.y;
            }
        }
        __syncthreads();
    }
    if (s0 + lr < cnt) {
        size_t grow = (size_t)(off + s0 + lr);
        __nv_bfloat16* dstP = (q < 2) ? g_Pg : g_Pu;
        int base = (q & 1) * 8;
#pragma unroll
        for (int j = 0; j < 8; j++)
            dstP[grow*64 + base + j] = __float2bfloat16(SCALING * acc[j]);
    }
}

__global__ __launch_bounds__(256, 2)
void proj_d_kernel(const float* __restrict__ dA) {
    int e = blockIdx.y;
    int cnt = g_counts[e];
    int s0 = blockIdx.x * 128;
    if (s0 >= cnt) return;
    int off = g_offsets[e];
    __shared__ __nv_bfloat16 Xs[128][128];
    __shared__ float Asm[16][128];
    int tid = threadIdx.x;
    int lr = tid >> 1, q = tid & 1;
    float acc[8];
#pragma unroll
    for (int j = 0; j < 8; j++) acc[j] = 0.f;

    for (int c = 0; c < 16; c++) {
        int k0 = c * 128;
#pragma unroll
        for (int i = 0; i < 8; i++) {
            int idx = tid + i * 256;
            int r = idx >> 7, k = idx & 127;
            Asm[r][k] = dA[((size_t)e*NR + r)*DIM + k0 + k];
        }
#pragma unroll
        for (int i = 0; i < 8; i++) {
            int idx = tid + i * 256;
            int r = idx >> 4, kc = (idx & 15) * 8;
            *(uint4*)&Xs[r][kc] = *(const uint4*)(g_A2 + (size_t)(off + s0 + r)*DIM + k0 + kc);
        }
        __syncthreads();
        for (int k = 0; k < 128; k += 2) {
            float2 xf = __bfloat1622float2(*(__nv_bfloat162*)&Xs[lr][k]);
#pragma unroll
            for (int j = 0; j < 8; j++) {
                float2 af = *(float2*)&Asm[q*8 + j][k];
                acc[j] += xf.x*af.x + xf.y*af.y;
            }
        }
        __syncthreads();
    }
    if (s0 + lr < cnt) {
        size_t grow = (size_t)(off + s0 + lr);
#pragma unroll
        for (int j = 0; j < 8; j++)
            g_Pd[grow*64 + q*8 + j] = __float2bfloat16(SCALING * acc[j]);
    }
}

// ----------------------- fused gate+up GEMM (mma.sync) ----------------------
// C_gate[128x64] and C_up[128x64] for the same (tile, n0); A tile shared.
// Stages 0-31: K main; stage 32: gate LoRA ext (A=Pg,B=LBg); 33: up ext.
__global__ __launch_bounds__(256, 2) void gu_gemm_kernel() {
    int tile = blockIdx.y;
    if (tile >= g_ntiles) return;
    int e = g_tile_e[tile];
    int rowbase = tile * 128;
    int n0 = blockIdx.x * 64;
    int tid = threadIdx.x;
    constexpr int NS = 34;

    extern __shared__ __nv_bfloat16 smem[];
    uint32_t smBase = (uint32_t)__cvta_generic_to_shared(smem);

    auto loadStage = [&](int s) {
        uint32_t buf = smBase + (uint32_t)(s % 3) * (GU_STG * 2);
        if (s < 32) {
            int k0 = s * BK;
#pragma unroll
            for (int it = 0; it < 4; it++) {           // A: 1024 x 16B
                int c = tid + it * 256;
                int row = c >> 3, ch = c & 7;
                uint32_t d = buf + (uint32_t)(row*64 + ((ch ^ (row & 7)) * 8)) * 2;
                cpa16(d, g_Xg + (size_t)(rowbase + row)*DIM + k0 + ch*8);
            }
#pragma unroll
            for (int it = 0; it < 2; it++) {           // Bg: 512 x 16B
                int c = tid + it * 256;
                int row = c >> 3, ch = c & 7;
                uint32_t d = buf + (uint32_t)(8192 + row*64 + ((ch ^ (row & 7)) * 8)) * 2;
                cpa16(d, g_Wgb + ((size_t)e*DIM + n0 + row)*DIM + k0 + ch*8);
            }
#pragma unroll
            for (int it = 0; it < 2; it++) {           // Bu
                int c = tid + it * 256;
                int row = c >> 3, ch = c & 7;
                uint32_t d = buf + (uint32_t)(12288 + row*64 + ((ch ^ (row & 7)) * 8)) * 2;
                cpa16(d, g_Wub + ((size_t)e*DIM + n0 + row)*DIM + k0 + ch*8);
            }
        } else {
            const __nv_bfloat16* P  = (s == 32) ? g_Pg  : g_Pu;
            const __nv_bfloat16* LB = (s == 32) ? g_LBg : g_LBu;
            uint32_t boff = (s == 32) ? 8192u : 12288u;
#pragma unroll
            for (int it = 0; it < 4; it++) {
                int c = tid + it * 256;
                int row = c >> 3, ch = c & 7;
                uint32_t d = buf + (uint32_t)(row*64 + ((ch ^ (row & 7)) * 8)) * 2;
                cpa16(d, P + (size_t)(rowbase + row)*64 + ch*8);
            }
#pragma unroll
            for (int it = 0; it < 2; it++) {
                int c = tid + it * 256;
                int row = c >> 3, ch = c & 7;
                uint32_t d = buf + (uint32_t)(boff + row*64 + ((ch ^ (row & 7)) * 8)) * 2;
                cpa16(d, LB + ((size_t)e*DIM + n0 + row)*64 + ch*8);
            }
        }
    };

    float ag[2][4][4], au[2][4][4];
#pragma unroll
    for (int mt = 0; mt < 2; mt++)
#pragma unroll
        for (int nt = 0; nt < 4; nt++)
#pragma unroll
            for (int i = 0; i < 4; i++) { ag[mt][nt][i] = 0.f; au[mt][nt][i] = 0.f; }

    int lane = tid & 31, warp = tid >> 5;
    int wm = warp & 3, wn = warp >> 2;    // 4x2 warps; per-warp 32 rows x 32 cols

    loadStage(0); CP_COMMIT;
    loadStage(1); CP_COMMIT;

    for (int s = 0; s < NS; s++) {
        cp_wait<1>();
        __syncthreads();
        if (s + 2 < NS) loadStage(s + 2);
        CP_COMMIT;

        uint32_t buf = smBase + (uint32_t)(s % 3) * (GU_STG * 2);
        bool doG = (s != 33), doU = (s != 32);
#pragma unroll
        for (int kk = 0; kk < BK; kk += 16) {
            int kh = kk + ((lane >> 4) << 3);
            unsigned af[2][4];
#pragma unroll
            for (int mt = 0; mt < 2; mt++) {
                int arow = wm*32 + mt*16 + (lane & 15);
                uint32_t a = buf + (uint32_t)(arow*64 +
                              (((kh >> 3) ^ (arow & 7)) << 3)) * 2;
                ldsm4(af[mt][0], af[mt][1], af[mt][2], af[mt][3], a);
            }
            if (doG) {
                unsigned bg[4][2];
#pragma unroll
                for (int p = 0; p < 2; p++) {
                    int brow = wn*32 + p*16 + (lane & 15);
                    uint32_t b = buf + (uint32_t)(8192 + brow*64 +
                                  (((kh >> 3) ^ (brow & 7)) << 3)) * 2;
                    unsigned q0, q1, q2, q3;
                    ldsm4(q0, q1, q2, q3, b);
                    bg[2*p][0] = q0; bg[2*p][1] = q2;
                    bg[2*p+1][0] = q1; bg[2*p+1][1] = q3;
                }
#pragma unroll
                for (int mt = 0; mt < 2; mt++)
#pragma unroll
                    for (int nt = 0; nt < 4; nt++)
                        mma16816(ag[mt][nt], af[mt], bg[nt]);
            }
            if (doU) {
                unsigned bu[4][2];
#pragma unroll
                for (int p = 0; p < 2; p++) {
                    int brow = wn*32 + p*16 + (lane & 15);
                    uint32_t b = buf + (uint32_t)(12288 + brow*64 +
                                  (((kh >> 3) ^ (brow & 7)) << 3)) * 2;
                    unsigned q0, q1, q2, q3;
                    ldsm4(q0, q1, q2, q3, b);
                    bu[2*p][0] = q0; bu[2*p][1] = q2;
                    bu[2*p+1][0] = q1; bu[2*p+1][1] = q3;
                }
#pragma unroll
                for (int mt = 0; mt < 2; mt++)
#pragma unroll
                    for (int nt = 0; nt < 4; nt++)
                        mma16816(au[mt][nt], af[mt], bu[nt]);
            }
        }
    }

    // epilogue: a = silu(g) * u -> g_A2 bf16
    int g = lane >> 2, t4 = lane & 3;
#pragma unroll
    for (int mt = 0; mt < 2; mt++) {
#pragma unroll
        for (int hrow = 0; hrow < 2; hrow++) {
            int r = wm*32 + mt*16 + g + hrow*8;
            __nv_bfloat16* dst = g_A2 + (size_t)(rowbase + r)*DIM + n0;
#pragma unroll
            for (int nt = 0; nt < 4; nt++) {
                int c = wn*32 + nt*8 + 2*t4;
                float g0 = ag[mt][nt][hrow*2 + 0];
                float g1 = ag[mt][nt][hrow*2 + 1];
                float u0 = au[mt][nt][hrow*2 + 0];
                float u1 = au[mt][nt][hrow*2 + 1];
                float a0 = g0 / (1.f + expf(-g0)) * u0;
                float a1 = g1 / (1.f + expf(-g1)) * u1;
                __nv_bfloat162 p = __floats2bfloat162_rn(a0, a1);
                *(unsigned*)(dst + c) = *reinterpret_cast<unsigned*>(&p);
            }
        }
    }
}

// ----------------------------- down GEMM ------------------------------------
__global__ __launch_bounds__(256, 2) void d_gemm_kernel() {
    int tile = blockIdx.y;
    if (tile >= g_ntiles) return;
    int e = g_tile_e[tile];
    int rowbase = tile * 128;
    int n0 = blockIdx.x * 128;
    int tid = threadIdx.x;
    constexpr int NS = 33;

    extern __shared__ __nv_bfloat16 smem[];
    uint32_t smBase = (uint32_t)__cvta_generic_to_shared(smem);

    auto loadStage = [&](int s) {
        uint32_t buf = smBase + (uint32_t)(s % 3) * (D_STG * 2);
        bool ext = (s == 32);
        int k0 = s * BK;
#pragma unroll
        for (int it = 0; it < 4; it++) {               // A
            int c = tid + it * 256;
            int row = c >> 3, ch = c & 7;
            uint32_t d = buf + (uint32_t)(row*64 + ((ch ^ (row & 7)) * 8)) * 2;
            const __nv_bfloat16* src = ext
                ? g_Pd + (size_t)(rowbase + row)*64 + ch*8
                : g_A2 + (size_t)(rowbase + row)*DIM + k0 + ch*8;
            cpa16(d, src);
        }
#pragma unroll
        for (int it = 0; it < 4; it++) {               // B
            int c = tid + it * 256;
            int row = c >> 3, ch = c & 7;
            uint32_t d = buf + (uint32_t)(8192 + row*64 + ((ch ^ (row & 7)) * 8)) * 2;
            const __nv_bfloat16* src = ext
                ? g_LBd + ((size_t)e*DIM + n0 + row)*64 + ch*8
                : g_Wdb + ((size_t)e*DIM + n0 + row)*DIM + k0 + ch*8;
            cpa16(d, src);
        }
    };

    float acc[2][8][4];
#pragma unroll
    for (int mt = 0; mt < 2; mt++)
#pragma unroll
        for (int nt = 0; nt < 8; nt++)
#pragma unroll
            for (int i = 0; i < 4; i++) acc[mt][nt][i] = 0.f;

    int lane = tid & 31, warp = tid >> 5;
    int wm = warp & 3, wn = warp >> 2;    // warp tile 32 x 64

    loadStage(0); CP_COMMIT;
    loadStage(1); CP_COMMIT;

    for (int s = 0; s < NS; s++) {
        cp_wait<1>();
        __syncthreads();
        if (s + 2 < NS) loadStage(s + 2);
        CP_COMMIT;

        uint32_t buf = smBase + (uint32_t)(s % 3) * (D_STG * 2);
#pragma unroll
        for (int kk = 0; kk < BK; kk += 16) {
            int kh = kk + ((lane >> 4) << 3);
            unsigned af[2][4];
#pragma unroll
            for (int mt = 0; mt < 2; mt++) {
                int arow = wm*32 + mt*16 + (lane & 15);
                uint32_t a = buf + (uint32_t)(arow*64 +
                              (((kh >> 3) ^ (arow & 7)) << 3)) * 2;
                ldsm4(af[mt][0], af[mt][1], af[mt][2], af[mt][3], a);
            }
            unsigned bq[8][2];
#pragma unroll
            for (int p = 0; p < 4; p++) {
                int brow = wn*64 + p*16 + (lane & 15);
                uint32_t b = buf + (uint32_t)(8192 + brow*64 +
                              (((kh >> 3) ^ (brow & 7)) << 3)) * 2;
                unsigned q0, q1, q2, q3;
                ldsm4(q0, q1, q2, q3, b);
                bq[2*p][0]   = q0; bq[2*p][1]   = q2;
                bq[2*p+1][0] = q1; bq[2*p+1][1] = q3;
            }
#pragma unroll
            for (int mt = 0; mt < 2; mt++)
#pragma unroll
                for (int nt = 0; nt < 8; nt++)
                    mma16816(acc[mt][nt], af[mt], bq[nt]);
        }
    }

    int g = lane >> 2, t4 = lane & 3;
#pragma unroll
    for (int mt = 0; mt < 2; mt++) {
#pragma unroll
        for (int hrow = 0; hrow < 2; hrow++) {
            int r = wm*32 + mt*16 + g + hrow*8;
            float* dst = g_D + (size_t)(rowbase + r)*DIM + n0;
#pragma unroll
            for (int nt = 0; nt < 8; nt++) {
                int c = wn*64 + nt*8 + 2*t4;
                *(float2*)(dst + c) =
                    make_float2(acc[mt][nt][hrow*2], acc[mt][nt][hrow*2 + 1]);
            }
        }
    }
}

// --------------------------- combine + loss ---------------------------------
__global__ void combine_kernel(const float* __restrict__ Xh,
                               const float* __restrict__ alpha,
                               float* __restrict__ out) {
    int t = blockIdx.x;
    int e0 = g_re[2*t], e1 = g_re[2*t+1];
    size_t r0 = (size_t)(g_offsets[e0] + g_rs[2*t]) * DIM;
    size_t r1 = (size_t)(g_offsets[e1] + g_rs[2*t+1]) * DIM;
    float al = alpha[0];
    float w0 = g_rg[2*t] * al, w1 = g_rg[2*t+1] * al;
    const float4* h4 = (const float4*)(Xh + (size_t)t * DIM);
    const float4* d0 = (const float4*)(g_D + r0);
    const float4* d1 = (const float4*)(g_D + r1);
    float4* o4 = (float4*)(out + (size_t)t * DIM);
    for (int i = threadIdx.x; i < DIM/4; i += blockDim.x) {
        float4 h = h4[i], a = d0[i], b = d1[i], r;
        r.x = h.x + w0*a.x + w1*b.x;
        r.y = h.y + w0*a.y + w1*b.y;
        r.z = h.z + w0*a.z + w1*b.z;
        r.w = h.w + w0*a.w + w1*b.w;
        o4[i] = r;
    }
}

__global__ void loss_kernel(float* __restrict__ out, int idx) {
    if (threadIdx.x == 0) {
        float s = 0.f;
        for (int e = 0; e < NE; e++) s += g_importance[e] * (float)g_counts[e];
        float lb = AUXC * ((float)NE * s / ((float)T_TOK * (float)T_TOK));
        float z  = ZC * (g_zsum / (float)T_TOK);
        out[idx] = lb + z;
    }
}

// ------------------------------- launcher -----------------------------------
extern "C" void kernel_launch(void* const* d_in, const int* in_sizes, int n_in,
                              void* d_out, int out_size) {
    const float* X      = (const float*)d_in[0];
    const float* Wg     = (const float*)d_in[1];
    const float* gate_w = (const float*)d_in[2];
    const float* gate_A = (const float*)d_in[3];
    const float* gate_B = (const float*)d_in[4];
    const float* up_w   = (const float*)d_in[5];
    const float* up_A   = (const float*)d_in[6];
    const float* up_B   = (const float*)d_in[7];
    const float* down_w = (const float*)d_in[8];
    const float* down_A = (const float*)d_in[9];
    const float* down_B = (const float*)d_in[10];
    const float* alpha  = (const float*)d_in[11];
    float* out = (float*)d_out;

    cudaFuncSetAttribute(gu_gemm_kernel, cudaFuncAttributeMaxDynamicSharedMemorySize, GU_SMEM);
    cudaFuncSetAttribute(d_gemm_kernel,  cudaFuncAttributeMaxDynamicSharedMemorySize, D_SMEM);

    __nv_bfloat16 *dWgb, *dWub, *dWdb, *dLBg, *dLBu, *dLBd;
    cudaGetSymbolAddress((void**)&dWgb, g_Wgb);
    cudaGetSymbolAddress((void**)&dWub, g_Wub);
    cudaGetSymbolAddress((void**)&dWdb, g_Wdb);
    cudaGetSymbolAddress((void**)&dLBg, g_LBg);
    cudaGetSymbolAddress((void**)&dLBu, g_LBu);
    cudaGetSymbolAddress((void**)&dLBd, g_LBd);

    int n4W = NE*DIM*DIM/4;
    f2b_kernel<<<(n4W+255)/256, 256>>>((const float4*)gate_w, (uint2*)dWgb, n4W);
    f2b_kernel<<<(n4W+255)/256, 256>>>((const float4*)up_w,   (uint2*)dWub, n4W);
    f2b_kernel<<<(n4W+255)/256, 256>>>((const float4*)down_w, (uint2*)dWdb, n4W);
    int nLB = NE*DIM*64;
    lbpad_kernel<<<(nLB+255)/256, 256>>>(gate_B, dLBg);
    lbpad_kernel<<<(nLB+255)/256, 256>>>(up_B,   dLBu);
    lbpad_kernel<<<(nLB+255)/256, 256>>>(down_B, dLBd);

    init_kernel<<<1, 32>>>();
    router_kernel<<<T_TOK/8, 256>>>(X, Wg);
    offsets_kernel<<<1, 1>>>();
    gather_kernel<<<PADROWS, 256>>>(X);

    dim3 pg(T_TOK/64, NE);
    proj_gu_kernel<<<pg, 256>>>(gate_A, up_A);

    dim3 gugrid(DIM/64, MAXTILES);
    gu_gemm_kernel<<<gugrid, 256, GU_SMEM>>>();     // fused gate+up -> g_A2

    dim3 pd(T_TOK/128, NE);
    proj_d_kernel<<<pd, 256>>>(down_A);

    dim3 dgrid(DIM/128, MAXTILES);
    d_gemm_kernel<<<dgrid, 256, D_SMEM>>>();        // down -> g_D

    combine_kernel<<<T_TOK, 256>>>(X, alpha, out);
    loss_kernel<<<1, 1>>>(out, out_size - 1);
}